// round 8
// baseline (speedup 1.0000x reference)
#include <cuda_runtime.h>
#include <cstdint>

#define N_NODES 100000
#define N_EDGES 1600000
#define CH      128

typedef unsigned long long ull;

// Scratch (static device globals — no allocation in kernel_launch)
__device__ __align__(16) float g_h[(size_t)N_NODES * CH];   // h = x W^T + b  (51.2 MB)
__device__ int g_deg[N_NODES];
__device__ int g_any_hi;   // statically 0; reset by k_sniff_fin each replay
__device__ int g_is64;     // 1 if edge_index is int64

// --------------------------------------- sniff dtype + init degree (fused) --
// Thread t: (a) if t < N_NODES, g_deg[t] = 1 (self-loop); (b) sample one odd
// 32-bit word of the edge buffer — int64 data has all-zero high halves.
__global__ void k_sniff_deg(const int* __restrict__ w) {
    int t = blockIdx.x * blockDim.x + threadIdx.x;      // 100096 threads
    if (t < N_NODES) g_deg[t] = 1;
    int i = (int)(((long long)t * 1599983LL) % 1600000LL);
    if (w[2 * i + 1] != 0) g_any_hi = 1;
}

__global__ void k_sniff_fin() {
    g_is64 = (g_any_hi == 0);
    g_any_hi = 0;                       // reset for next graph replay
}

__device__ __forceinline__ void edge_params(int* stride, int* dbase) {
    int f = g_is64;
    *stride = f ? 2 : 1;
    *dbase  = f ? 2 * N_EDGES : N_EDGES;
}

// ---------------------------------------------------------------- degree ----
__global__ void k_deg_count(const int* __restrict__ ei) {
    int e = blockIdx.x * blockDim.x + threadIdx.x;
    if (e >= N_EDGES) return;
    int stride, dbase; edge_params(&stride, &dbase);
    atomicAdd(&g_deg[ei[dbase + stride * e]], 1);
}

// ------------------------------------------------------------------ GEMM ----
// h[m][o] = b[o] + sum_k x[m][k] * W[o][k];  fused: out[m] = h[m]/deg[m].
// 128 threads, 4 warps, 32 rows/block (grid 3125 exact). Microtile 8x4.
// a-operand: broadcast LDS.128 along k; b: spread LDS.128. FFMA2 inner product.
__global__ void __launch_bounds__(128) k_gemm(const float* __restrict__ x,
                                              const float* __restrict__ W,
                                              const float* __restrict__ bias,
                                              float* __restrict__ out) {
    __shared__ float xs[32][CH];   // 16 KB input rows
    __shared__ float wt[32][CH];   // 16 KB: wt[kk][o] = W[o][kc+kk]

    const int t    = threadIdx.x;
    const int w    = t >> 5;       // 0..3
    const int lane = t & 31;

    const float4* xg = (const float4*)(x + (size_t)blockIdx.x * 32 * CH);
    #pragma unroll
    for (int i = 0; i < 8; i++) {
        int v = t + i * 128;
        ((float4*)&xs[0][0])[v] = xg[v];
    }

    float4 b4 = ((const float4*)bias)[lane];
    ull acc[8][2];
    #pragma unroll
    for (int r = 0; r < 8; r++) {
        asm("mov.b64 %0, {%1, %2};" : "=l"(acc[r][0])
            : "r"(__float_as_uint(b4.x)), "r"(__float_as_uint(b4.y)));
        asm("mov.b64 %0, {%1, %2};" : "=l"(acc[r][1])
            : "r"(__float_as_uint(b4.z)), "r"(__float_as_uint(b4.w)));
    }

    for (int kc = 0; kc < CH; kc += 32) {
        __syncthreads();
        #pragma unroll
        for (int i = 0; i < 8; i++) {
            float4 f = *(const float4*)(W + (size_t)t * CH + kc + i * 4);
            wt[i * 4 + 0][t] = f.x;
            wt[i * 4 + 1][t] = f.y;
            wt[i * 4 + 2][t] = f.z;
            wt[i * 4 + 3][t] = f.w;
        }
        __syncthreads();

        #pragma unroll
        for (int g = 0; g < 8; g++) {          // 4 k-steps per group
            const int k0 = g * 4;
            ulonglong2 bq0 = *(const ulonglong2*)&wt[k0 + 0][lane * 4];
            ulonglong2 bq1 = *(const ulonglong2*)&wt[k0 + 1][lane * 4];
            ulonglong2 bq2 = *(const ulonglong2*)&wt[k0 + 2][lane * 4];
            ulonglong2 bq3 = *(const ulonglong2*)&wt[k0 + 3][lane * 4];
            #pragma unroll
            for (int r = 0; r < 8; r++) {
                float4 a = *(const float4*)&xs[w * 8 + r][kc + k0]; // broadcast
                ull a0, a1, a2, a3;
                asm("mov.b64 %0, {%1, %1};" : "=l"(a0) : "r"(__float_as_uint(a.x)));
                asm("mov.b64 %0, {%1, %1};" : "=l"(a1) : "r"(__float_as_uint(a.y)));
                asm("mov.b64 %0, {%1, %1};" : "=l"(a2) : "r"(__float_as_uint(a.z)));
                asm("mov.b64 %0, {%1, %1};" : "=l"(a3) : "r"(__float_as_uint(a.w)));
                asm("fma.rn.f32x2 %0, %1, %2, %0;" : "+l"(acc[r][0]) : "l"(a0), "l"(bq0.x));
                asm("fma.rn.f32x2 %0, %1, %2, %0;" : "+l"(acc[r][1]) : "l"(a0), "l"(bq0.y));
                asm("fma.rn.f32x2 %0, %1, %2, %0;" : "+l"(acc[r][0]) : "l"(a1), "l"(bq1.x));
                asm("fma.rn.f32x2 %0, %1, %2, %0;" : "+l"(acc[r][1]) : "l"(a1), "l"(bq1.y));
                asm("fma.rn.f32x2 %0, %1, %2, %0;" : "+l"(acc[r][0]) : "l"(a2), "l"(bq2.x));
                asm("fma.rn.f32x2 %0, %1, %2, %0;" : "+l"(acc[r][1]) : "l"(a2), "l"(bq2.y));
                asm("fma.rn.f32x2 %0, %1, %2, %0;" : "+l"(acc[r][0]) : "l"(a3), "l"(bq3.x));
                asm("fma.rn.f32x2 %0, %1, %2, %0;" : "+l"(acc[r][1]) : "l"(a3), "l"(bq3.y));
            }
        }
    }

    #pragma unroll
    for (int r = 0; r < 8; r++) {
        unsigned int r0, r1, r2, r3;
        asm("mov.b64 {%0, %1}, %2;" : "=r"(r0), "=r"(r1) : "l"(acc[r][0]));
        asm("mov.b64 {%0, %1}, %2;" : "=r"(r2), "=r"(r3) : "l"(acc[r][1]));
        float4 hv = make_float4(__uint_as_float(r0), __uint_as_float(r1),
                                __uint_as_float(r2), __uint_as_float(r3));
        size_t row = (size_t)blockIdx.x * 32 + w * 8 + r;
        ((float4*)g_h)[row * 32 + lane] = hv;
        float invd = 1.0f / (float)g_deg[row];
        ((float4*)out)[row * 32 + lane] =
            make_float4(hv.x * invd, hv.y * invd, hv.z * invd, hv.w * invd);
    }
}

// ------------------------------------------------------------ edge scatter --
// One warp per edge: norm computed inline from g_deg (k_isd eliminated);
// gather h[src] (float4/lane), vector red.add.v4 into out[dst].
__global__ void __launch_bounds__(256) k_edges(const int* __restrict__ ei,
                                               float* __restrict__ out) {
    int e    = (blockIdx.x << 3) + (threadIdx.x >> 5);
    int lane = threadIdx.x & 31;
    if (e >= N_EDGES) return;

    int stride, dbase; edge_params(&stride, &dbase);
    int s = ei[stride * e];
    int d = ei[dbase + stride * e];
    float nrm = rsqrtf((float)g_deg[s] * (float)g_deg[d]);

    float4 h = ((const float4*)g_h)[(size_t)s * 32 + lane];
    float* p = out + (size_t)d * CH + lane * 4;      // 16B aligned
    asm volatile("red.global.add.v4.f32 [%0], {%1, %2, %3, %4};"
                 :: "l"(p), "f"(h.x * nrm), "f"(h.y * nrm),
                    "f"(h.z * nrm), "f"(h.w * nrm)
                 : "memory");
}

// ------------------------------------------------------------------- glue ---
extern "C" void kernel_launch(void* const* d_in, const int* in_sizes, int n_in,
                              void* d_out, int out_size) {
    const float* x  = (const float*)d_in[0];
    const int*   ei = (const int*)d_in[1];     // int32 or int64 (sniffed)
    const float* W  = (const float*)d_in[2];
    const float* b  = (const float*)d_in[3];
    float* out = (float*)d_out;

    k_sniff_deg<<<(N_NODES + 255) / 256, 256>>>(ei);   // launch 0
    k_sniff_fin<<<1, 1>>>();                           // launch 1
    k_deg_count<<<(N_EDGES + 255) / 256, 256>>>(ei);   // launch 2
    k_gemm<<<N_NODES / 32, 128>>>(x, W, b, out);       // launch 3 (profiled)
    k_edges<<<N_EDGES / 8, 256>>>(ei, out);            // launch 4
}

// round 10
// speedup vs baseline: 1.0846x; 1.0846x over previous
#include <cuda_runtime.h>
#include <cuda_fp16.h>
#include <cstdint>

#define N_NODES 100000
#define N_EDGES 1600000
#define CH      128

typedef unsigned long long ull;

// Scratch (static device globals — no allocation in kernel_launch)
__device__ __align__(16) __half g_h16[(size_t)N_NODES * CH];  // 25.6 MB fp16 h
__device__ int g_deg[N_NODES];
__device__ int g_any_hi;   // statically 0; reset by k_sniff_fin each replay
__device__ int g_is64;     // 1 if edge_index is int64

// --------------------------------------- sniff dtype + init degree (fused) --
__global__ void k_sniff_deg(const int* __restrict__ w) {
    int t = blockIdx.x * blockDim.x + threadIdx.x;      // 100096 threads
    if (t < N_NODES) g_deg[t] = 1;
    int i = (int)(((long long)t * 1599983LL) % 1600000LL);
    if (w[2 * i + 1] != 0) g_any_hi = 1;
}

__global__ void k_sniff_fin() {
    g_is64 = (g_any_hi == 0);
    g_any_hi = 0;                       // reset for next graph replay
}

__device__ __forceinline__ void edge_params(int* stride, int* dbase) {
    int f = g_is64;
    *stride = f ? 2 : 1;
    *dbase  = f ? 2 * N_EDGES : N_EDGES;
}

// ---------------------------------------------------------------- degree ----
__global__ void k_deg_count(const int* __restrict__ ei) {
    int e = blockIdx.x * blockDim.x + threadIdx.x;
    if (e >= N_EDGES) return;
    int stride, dbase; edge_params(&stride, &dbase);
    atomicAdd(&g_deg[ei[dbase + stride * e]], 1);
}

// ------------------------------------------------------------------ GEMM ----
// h[m][o] = b[o] + sum_k x[m][k] * W[o][k]
// Fused epilogue: out[m] = h[m]/deg[m] (exact fp32 self term) and
// g_h16[m] = fp16(h[m]) (scatter operand only).
// 128 threads, 4 warps, 32 rows/block (grid 3125). Microtile 8x4, FFMA2.
__global__ void __launch_bounds__(128) k_gemm(const float* __restrict__ x,
                                              const float* __restrict__ W,
                                              const float* __restrict__ bias,
                                              float* __restrict__ out) {
    __shared__ float xs[32][CH];   // 16 KB input rows
    __shared__ float wt[32][CH];   // 16 KB: wt[kk][o] = W[o][kc+kk]

    const int t    = threadIdx.x;
    const int w    = t >> 5;       // 0..3
    const int lane = t & 31;

    const float4* xg = (const float4*)(x + (size_t)blockIdx.x * 32 * CH);
    #pragma unroll
    for (int i = 0; i < 8; i++) {
        int v = t + i * 128;
        ((float4*)&xs[0][0])[v] = xg[v];
    }

    float4 b4 = ((const float4*)bias)[lane];
    ull acc[8][2];
    #pragma unroll
    for (int r = 0; r < 8; r++) {
        asm("mov.b64 %0, {%1, %2};" : "=l"(acc[r][0])
            : "r"(__float_as_uint(b4.x)), "r"(__float_as_uint(b4.y)));
        asm("mov.b64 %0, {%1, %2};" : "=l"(acc[r][1])
            : "r"(__float_as_uint(b4.z)), "r"(__float_as_uint(b4.w)));
    }

    for (int kc = 0; kc < CH; kc += 32) {
        __syncthreads();
        #pragma unroll
        for (int i = 0; i < 8; i++) {
            float4 f = *(const float4*)(W + (size_t)t * CH + kc + i * 4);
            wt[i * 4 + 0][t] = f.x;
            wt[i * 4 + 1][t] = f.y;
            wt[i * 4 + 2][t] = f.z;
            wt[i * 4 + 3][t] = f.w;
        }
        __syncthreads();

        #pragma unroll
        for (int g = 0; g < 8; g++) {          // 4 k-steps per group
            const int k0 = g * 4;
            ulonglong2 bq0 = *(const ulonglong2*)&wt[k0 + 0][lane * 4];
            ulonglong2 bq1 = *(const ulonglong2*)&wt[k0 + 1][lane * 4];
            ulonglong2 bq2 = *(const ulonglong2*)&wt[k0 + 2][lane * 4];
            ulonglong2 bq3 = *(const ulonglong2*)&wt[k0 + 3][lane * 4];
            #pragma unroll
            for (int r = 0; r < 8; r++) {
                float4 a = *(const float4*)&xs[w * 8 + r][kc + k0]; // broadcast
                ull a0, a1, a2, a3;
                asm("mov.b64 %0, {%1, %1};" : "=l"(a0) : "r"(__float_as_uint(a.x)));
                asm("mov.b64 %0, {%1, %1};" : "=l"(a1) : "r"(__float_as_uint(a.y)));
                asm("mov.b64 %0, {%1, %1};" : "=l"(a2) : "r"(__float_as_uint(a.z)));
                asm("mov.b64 %0, {%1, %1};" : "=l"(a3) : "r"(__float_as_uint(a.w)));
                asm("fma.rn.f32x2 %0, %1, %2, %0;" : "+l"(acc[r][0]) : "l"(a0), "l"(bq0.x));
                asm("fma.rn.f32x2 %0, %1, %2, %0;" : "+l"(acc[r][1]) : "l"(a0), "l"(bq0.y));
                asm("fma.rn.f32x2 %0, %1, %2, %0;" : "+l"(acc[r][0]) : "l"(a1), "l"(bq1.x));
                asm("fma.rn.f32x2 %0, %1, %2, %0;" : "+l"(acc[r][1]) : "l"(a1), "l"(bq1.y));
                asm("fma.rn.f32x2 %0, %1, %2, %0;" : "+l"(acc[r][0]) : "l"(a2), "l"(bq2.x));
                asm("fma.rn.f32x2 %0, %1, %2, %0;" : "+l"(acc[r][1]) : "l"(a2), "l"(bq2.y));
                asm("fma.rn.f32x2 %0, %1, %2, %0;" : "+l"(acc[r][0]) : "l"(a3), "l"(bq3.x));
                asm("fma.rn.f32x2 %0, %1, %2, %0;" : "+l"(acc[r][1]) : "l"(a3), "l"(bq3.y));
            }
        }
    }

    #pragma unroll
    for (int r = 0; r < 8; r++) {
        unsigned int r0, r1, r2, r3;
        asm("mov.b64 {%0, %1}, %2;" : "=r"(r0), "=r"(r1) : "l"(acc[r][0]));
        asm("mov.b64 {%0, %1}, %2;" : "=r"(r2), "=r"(r3) : "l"(acc[r][1]));
        float4 hv = make_float4(__uint_as_float(r0), __uint_as_float(r1),
                                __uint_as_float(r2), __uint_as_float(r3));
        size_t row = (size_t)blockIdx.x * 32 + w * 8 + r;

        // fp16 h for the scatter gather (25.6 MB total)
        __half2 p0 = __floats2half2_rn(hv.x, hv.y);
        __half2 p1 = __floats2half2_rn(hv.z, hv.w);
        uint2 pk;
        pk.x = *(unsigned int*)&p0;
        pk.y = *(unsigned int*)&p1;
        ((uint2*)g_h16)[row * 32 + lane] = pk;

        // exact fp32 self term
        float invd = 1.0f / (float)g_deg[row];
        ((float4*)out)[row * 32 + lane] =
            make_float4(hv.x * invd, hv.y * invd, hv.z * invd, hv.w * invd);
    }
}

// ------------------------------------------------------------ edge scatter --
// One warp per edge: gather fp16 h[src] (uint2 = 4 halves per lane, 256B/row),
// convert + scale in fp32, vector red.add.v4 into out[dst].
__global__ void __launch_bounds__(256) k_edges(const int* __restrict__ ei,
                                               float* __restrict__ out) {
    int e    = (blockIdx.x << 3) + (threadIdx.x >> 5);
    int lane = threadIdx.x & 31;
    if (e >= N_EDGES) return;

    int stride, dbase; edge_params(&stride, &dbase);
    int s = ei[stride * e];
    int d = ei[dbase + stride * e];
    float nrm = rsqrtf((float)g_deg[s] * (float)g_deg[d]);

    uint2 pk = ((const uint2*)g_h16)[(size_t)s * 32 + lane];
    float2 f0 = __half22float2(*(const __half2*)&pk.x);
    float2 f1 = __half22float2(*(const __half2*)&pk.y);

    float* p = out + (size_t)d * CH + lane * 4;      // 16B aligned
    asm volatile("red.global.add.v4.f32 [%0], {%1, %2, %3, %4};"
                 :: "l"(p), "f"(f0.x * nrm), "f"(f0.y * nrm),
                    "f"(f1.x * nrm), "f"(f1.y * nrm)
                 : "memory");
}

// ------------------------------------------------------------------- glue ---
extern "C" void kernel_launch(void* const* d_in, const int* in_sizes, int n_in,
                              void* d_out, int out_size) {
    const float* x  = (const float*)d_in[0];
    const int*   ei = (const int*)d_in[1];     // int32 or int64 (sniffed)
    const float* W  = (const float*)d_in[2];
    const float* b  = (const float*)d_in[3];
    float* out = (float*)d_out;

    k_sniff_deg<<<(N_NODES + 255) / 256, 256>>>(ei);   // launch 0
    k_sniff_fin<<<1, 1>>>();                           // launch 1
    k_deg_count<<<(N_EDGES + 255) / 256, 256>>>(ei);   // launch 2
    k_gemm<<<N_NODES / 32, 128>>>(x, W, b, out);       // launch 3 (profiled)
    k_edges<<<N_EDGES / 8, 256>>>(ei, out);            // launch 4
}